// round 1
// baseline (speedup 1.0000x reference)
#include <cuda_runtime.h>
#include <cuda_bf16.h>
#include <math.h>

// Problem constants
#define T_TOK   4096          // B*S
#define D_IN    4096
#define D_OUT   4096
#define N_EXP   8
#define RANK    16
#define TOPK    2
#define SCALING 2.0f          // 32/16
#define NJ      (N_EXP + N_EXP*RANK)   // 136 rows of the fused gate/lora_A weight

// ---------------- scratch (no allocation allowed -> __device__ globals) ----------------
__device__ float g_low[T_TOK * NJ];        // [t][136]: 0..7 gate logits, 8..135 low (e*16+r)
__device__ float g_c[T_TOK * 32];          // per-token combined coeffs: SCALING*w_k*low
__device__ int   g_eidx[T_TOK * 2];        // per-token selected experts

// ---------------- kernel 1: fused gate-logits + low-rank projections ----------------
// G[t, j] = x[t,:] . W[j,:]  where W = concat(gate_w, lora_A_flat) : [136, 4096]
// Block: 32 tokens x 136 outputs. 256 threads = 32 token-lanes x 8 j-groups of 17.
#define CH1 64
__global__ __launch_bounds__(256) void gate_low_kernel(
    const float* __restrict__ x,
    const float* __restrict__ gate_w,
    const float* __restrict__ lora_A)
{
    __shared__ float xs[32][CH1 + 1];
    __shared__ float ws[NJ][CH1 + 1];
    const int tid = threadIdx.x;
    const int t0  = blockIdx.x * 32;
    const int tl  = tid & 31;     // token lane
    const int jg  = tid >> 5;     // 0..7 -> j range [jg*17, jg*17+17)

    float acc[17];
#pragma unroll
    for (int i = 0; i < 17; i++) acc[i] = 0.f;

    for (int d0 = 0; d0 < D_IN; d0 += CH1) {
        // stage x chunk: 32*64 elems
        for (int i = tid; i < 32 * CH1; i += 256) {
            int r = i / CH1, c = i % CH1;
            xs[r][c] = x[(size_t)(t0 + r) * D_IN + d0 + c];
        }
        // stage W chunk: 136*64 elems
        for (int i = tid; i < NJ * CH1; i += 256) {
            int r = i / CH1, c = i % CH1;
            float v = (r < N_EXP) ? gate_w[(size_t)r * D_IN + d0 + c]
                                  : lora_A[(size_t)(r - N_EXP) * D_IN + d0 + c];
            ws[r][c] = v;
        }
        __syncthreads();
#pragma unroll 8
        for (int c = 0; c < CH1; c++) {
            float xv = xs[tl][c];
#pragma unroll
            for (int i = 0; i < 17; i++)
                acc[i] += xv * ws[jg * 17 + i][c];
        }
        __syncthreads();
    }
    const int t = t0 + tl;
#pragma unroll
    for (int i = 0; i < 17; i++)
        g_low[(size_t)t * NJ + jg * 17 + i] = acc[i];
}

// ---------------- kernel 2: top-2 + softmax + coefficient build ----------------
__global__ void route_kernel()
{
    int t = blockIdx.x * 256 + threadIdx.x;
    if (t >= T_TOK) return;
    const float* lg = g_low + (size_t)t * NJ;

    // top-1 (strict >, lowest index on ties -> matches lax.top_k stability)
    int i0 = 0; float v0 = lg[0];
#pragma unroll
    for (int e = 1; e < N_EXP; e++) { float v = lg[e]; if (v > v0) { v0 = v; i0 = e; } }
    // top-2
    int i1 = -1; float v1 = -INFINITY;
#pragma unroll
    for (int e = 0; e < N_EXP; e++) {
        if (e == i0) continue;
        float v = lg[e];
        if (v > v1) { v1 = v; i1 = e; }
    }
    // softmax over (v0, v1), v0 >= v1
    float e1 = expf(v1 - v0);
    float w0 = 1.f / (1.f + e1);
    float w1 = e1 * w0;

    g_eidx[t * 2 + 0] = i0;
    g_eidx[t * 2 + 1] = i1;
    float* c = g_c + (size_t)t * 32;
    const float* low0 = lg + N_EXP + i0 * RANK;
    const float* low1 = lg + N_EXP + i1 * RANK;
#pragma unroll
    for (int r = 0; r < RANK; r++) {
        c[r]        = SCALING * w0 * low0[r];
        c[16 + r]   = SCALING * w1 * low1[r];
    }
}

// ---------------- kernel 3: base GEMM out = x @ base_w^T + b ----------------
// 128x128 tile, 256 threads, 8x8 per-thread microtile (strided mapping for coalescing)
__global__ __launch_bounds__(256) void base_gemm_kernel(
    const float* __restrict__ A,      // x [T, D]
    const float* __restrict__ Bw,     // base_w [O, D]
    const float* __restrict__ bias,   // [O]
    float* __restrict__ out)          // [T, O]
{
    __shared__ float As[8][132];
    __shared__ float Bs[8][132];

    const int tid = threadIdx.x;
    const int tx = tid & 15;          // output-col lane
    const int ty = tid >> 4;          // token-row lane
    const int bt = blockIdx.y * 128;
    const int bo = blockIdx.x * 128;

    float acc[8][8];
#pragma unroll
    for (int i = 0; i < 8; i++)
#pragma unroll
        for (int j = 0; j < 8; j++) acc[i][j] = 0.f;

    const int lr = tid >> 1;          // 0..127 : row within tile
    const int lh = tid & 1;           // which half of the 8-wide K chunk
    const float* Aptr = A  + (size_t)(bt + lr) * D_IN + lh * 4;
    const float* Bptr = Bw + (size_t)(bo + lr) * D_IN + lh * 4;

    for (int d0 = 0; d0 < D_IN; d0 += 8) {
        float4 av = *(const float4*)(Aptr + d0);
        float4 bv = *(const float4*)(Bptr + d0);
        __syncthreads();   // previous iteration's compute done before smem overwrite
        As[lh * 4 + 0][lr] = av.x; As[lh * 4 + 1][lr] = av.y;
        As[lh * 4 + 2][lr] = av.z; As[lh * 4 + 3][lr] = av.w;
        Bs[lh * 4 + 0][lr] = bv.x; Bs[lh * 4 + 1][lr] = bv.y;
        Bs[lh * 4 + 2][lr] = bv.z; Bs[lh * 4 + 3][lr] = bv.w;
        __syncthreads();
#pragma unroll
        for (int kk = 0; kk < 8; kk++) {
            float a[8], b[8];
#pragma unroll
            for (int i = 0; i < 8; i++) a[i] = As[kk][ty + i * 16];
#pragma unroll
            for (int j = 0; j < 8; j++) b[j] = Bs[kk][tx + j * 16];
#pragma unroll
            for (int i = 0; i < 8; i++)
#pragma unroll
                for (int j = 0; j < 8; j++)
                    acc[i][j] += a[i] * b[j];
        }
    }

#pragma unroll
    for (int i = 0; i < 8; i++) {
        const int t = bt + ty + i * 16;
#pragma unroll
        for (int j = 0; j < 8; j++) {
            const int o = bo + tx + j * 16;
            out[(size_t)t * D_OUT + o] = acc[i][j] + bias[o];
        }
    }
}

// ---------------- kernel 4: LoRA epilogue out += sum_k c . lora_B[e_k] ----------------
__global__ __launch_bounds__(256) void lora_add_kernel(
    const float* __restrict__ lora_B,   // [E, O, R]
    float* __restrict__ out)
{
    const int t = blockIdx.y;
    const int o = blockIdx.x * 256 + threadIdx.x;

    __shared__ float cs[32];
    __shared__ int   es[2];
    if (threadIdx.x < 32) cs[threadIdx.x] = g_c[(size_t)t * 32 + threadIdx.x];
    if (threadIdx.x < 2)  es[threadIdx.x] = g_eidx[t * 2 + threadIdx.x];
    __syncthreads();

    const float4* b0 = (const float4*)(lora_B + ((size_t)es[0] * D_OUT + o) * RANK);
    const float4* b1 = (const float4*)(lora_B + ((size_t)es[1] * D_OUT + o) * RANK);
    float s = 0.f;
#pragma unroll
    for (int q = 0; q < 4; q++) {
        float4 v = b0[q];
        s += cs[q * 4 + 0] * v.x + cs[q * 4 + 1] * v.y
           + cs[q * 4 + 2] * v.z + cs[q * 4 + 3] * v.w;
    }
#pragma unroll
    for (int q = 0; q < 4; q++) {
        float4 v = b1[q];
        s += cs[16 + q * 4 + 0] * v.x + cs[16 + q * 4 + 1] * v.y
           + cs[16 + q * 4 + 2] * v.z + cs[16 + q * 4 + 3] * v.w;
    }
    out[(size_t)t * D_OUT + o] += s;
}

// ---------------- launch ----------------
extern "C" void kernel_launch(void* const* d_in, const int* in_sizes, int n_in,
                              void* d_out, int out_size)
{
    const float* x      = (const float*)d_in[0];
    const float* gate_w = (const float*)d_in[1];
    const float* base_w = (const float*)d_in[2];
    const float* base_b = (const float*)d_in[3];
    const float* lora_A = (const float*)d_in[4];
    const float* lora_B = (const float*)d_in[5];
    float* out = (float*)d_out;

    gate_low_kernel<<<T_TOK / 32, 256>>>(x, gate_w, lora_A);
    route_kernel<<<(T_TOK + 255) / 256, 256>>>();
    base_gemm_kernel<<<dim3(D_OUT / 128, T_TOK / 128), 256>>>(x, base_w, base_b, out);
    lora_add_kernel<<<dim3(D_OUT / 256, T_TOK), 256>>>(lora_B, out);
}

// round 3
// speedup vs baseline: 4.0131x; 4.0131x over previous
#include <cuda_runtime.h>
#include <cuda_fp16.h>
#include <math.h>
#include <stdint.h>

// ---------------- problem constants ----------------
#define T_TOK   4096
#define D_IN    4096
#define D_OUT   4096
#define N_EXP   8
#define RANK    16
#define SCALING 2.0f
#define NJ      (N_EXP + N_EXP*RANK)   // 136

// GEMM tiling
#define TILE_M  128
#define TILE_N  128
#define KC      64                     // fp16 K elems per chunk (128 B rows)
#define NCHUNK_BASE (D_IN / KC)        // 64
#define NCHUNK  (NCHUNK_BASE + 2)      // + 2 LoRA chunks (128-wide fused lora K)

#define A_BYTES (TILE_M * 128)         // 16 KB
#define B_BYTES (TILE_N * 128)         // 16 KB
#define STAGE_BYTES (A_BYTES + B_BYTES)  // 32 KB
#define NSTAGE  2

// ---------------- device scratch (no allocs allowed) ----------------
__device__ __half g_xh[(size_t)T_TOK * D_IN];
__device__ __half g_wh[(size_t)D_OUT * D_IN];
__device__ __half g_L [(size_t)D_OUT * 128];
__device__ __half g_C [(size_t)T_TOK * 128];
__device__ float  g_low[(size_t)T_TOK * NJ];

// ---------------- helpers ----------------
__device__ __forceinline__ uint32_t smem_u32(const void* p) {
    uint32_t a;
    asm("{ .reg .u64 t; cvta.to.shared.u64 t, %1; cvt.u32.u64 %0, t; }" : "=r"(a) : "l"(p));
    return a;
}
__device__ __forceinline__ void cp16(uint32_t dst, const void* src) {
    asm volatile("cp.async.cg.shared.global [%0], [%1], 16;" :: "r"(dst), "l"(src));
}
__device__ __forceinline__ void cp_commit() { asm volatile("cp.async.commit_group;" ::: "memory"); }
__device__ __forceinline__ void cp_wait1()  { asm volatile("cp.async.wait_group 1;" ::: "memory"); }
__device__ __forceinline__ void cp_wait0()  { asm volatile("cp.async.wait_group 0;" ::: "memory"); }

__device__ __forceinline__ void ldsm_x4(uint32_t (&r)[4], uint32_t addr) {
    asm volatile("ldmatrix.sync.aligned.m8n8.x4.shared.b16 {%0,%1,%2,%3}, [%4];"
                 : "=r"(r[0]), "=r"(r[1]), "=r"(r[2]), "=r"(r[3]) : "r"(addr));
}
__device__ __forceinline__ void mma16816(float (&d)[4], const uint32_t (&a)[4], const uint32_t b0, const uint32_t b1) {
    asm volatile(
        "mma.sync.aligned.m16n8k16.row.col.f32.f16.f16.f32 "
        "{%0,%1,%2,%3},{%4,%5,%6,%7},{%8,%9},{%0,%1,%2,%3};"
        : "+f"(d[0]), "+f"(d[1]), "+f"(d[2]), "+f"(d[3])
        : "r"(a[0]), "r"(a[1]), "r"(a[2]), "r"(a[3]), "r"(b0), "r"(b1));
}

// ---------------- convert f32 -> fp16 ----------------
__global__ __launch_bounds__(256) void tohalf_kernel(
    const float* __restrict__ src, __half* __restrict__ dst, int n4)
{
    int i = blockIdx.x * 256 + threadIdx.x;
    if (i >= n4) return;
    float4 v = ((const float4*)src)[i];
    __half2 h0 = __floats2half2_rn(v.x, v.y);
    __half2 h1 = __floats2half2_rn(v.z, v.w);
    ((__half2*)dst)[i * 2]     = h0;
    ((__half2*)dst)[i * 2 + 1] = h1;
}

// ---------------- pack lora_B [E,O,R] -> L[o, e*16+r] fp16 ----------------
__global__ __launch_bounds__(256) void pack_L_kernel(const float* __restrict__ lora_B)
{
    int idx = blockIdx.x * 256 + threadIdx.x;   // over 4096*128
    if (idx >= D_OUT * 128) return;
    int o = idx >> 7, j = idx & 127;
    int e = j >> 4, r = j & 15;
    g_L[idx] = __float2half(lora_B[((size_t)e * D_OUT + o) * RANK + r]);
}

// ---------------- kernel 1: gate logits + low projections (fp32 SIMT) ----------------
#define CH1 64
__global__ __launch_bounds__(256) void gate_low_kernel(
    const float* __restrict__ x, const float* __restrict__ gate_w, const float* __restrict__ lora_A)
{
    __shared__ float xs[32][CH1 + 1];
    __shared__ float ws[NJ][CH1 + 1];
    const int tid = threadIdx.x;
    const int t0 = blockIdx.x * 32;
    const int tl = tid & 31;
    const int jg = tid >> 5;

    float acc[17];
#pragma unroll
    for (int i = 0; i < 17; i++) acc[i] = 0.f;

    for (int d0 = 0; d0 < D_IN; d0 += CH1) {
        for (int i = tid; i < 32 * CH1; i += 256) {
            int r = i / CH1, c = i % CH1;
            xs[r][c] = x[(size_t)(t0 + r) * D_IN + d0 + c];
        }
        for (int i = tid; i < NJ * CH1; i += 256) {
            int r = i / CH1, c = i % CH1;
            ws[r][c] = (r < N_EXP) ? gate_w[(size_t)r * D_IN + d0 + c]
                                   : lora_A[(size_t)(r - N_EXP) * D_IN + d0 + c];
        }
        __syncthreads();
#pragma unroll 8
        for (int c = 0; c < CH1; c++) {
            float xv = xs[tl][c];
#pragma unroll
            for (int i = 0; i < 17; i++) acc[i] += xv * ws[jg * 17 + i][c];
        }
        __syncthreads();
    }
    const int t = t0 + tl;
#pragma unroll
    for (int i = 0; i < 17; i++) g_low[(size_t)t * NJ + jg * 17 + i] = acc[i];
}

// ---------------- kernel 2: top-2 softmax -> dense coeff row C[t,128] fp16 ----------------
__global__ void route_kernel()
{
    int t = blockIdx.x * 256 + threadIdx.x;
    if (t >= T_TOK) return;
    const float* lg = g_low + (size_t)t * NJ;

    int i0 = 0; float v0 = lg[0];
#pragma unroll
    for (int e = 1; e < N_EXP; e++) { float v = lg[e]; if (v > v0) { v0 = v; i0 = e; } }
    int i1 = -1; float v1 = -INFINITY;
#pragma unroll
    for (int e = 0; e < N_EXP; e++) {
        if (e == i0) continue;
        float v = lg[e];
        if (v > v1) { v1 = v; i1 = e; }
    }
    float e1 = expf(v1 - v0);
    float w0 = 1.f / (1.f + e1);
    float w1 = e1 * w0;

    __half* c = g_C + (size_t)t * 128;
#pragma unroll
    for (int e = 0; e < N_EXP; e++) {
        float w = (e == i0) ? SCALING * w0 : (e == i1) ? SCALING * w1 : 0.f;
        const float* low = lg + N_EXP + e * RANK;
#pragma unroll
        for (int r = 0; r < RANK; r++)
            c[e * RANK + r] = __float2half(w * low[r]);
    }
}

// ---------------- kernel 3: fused fp16 HMMA GEMM: out = x@W^T + b + C@L^T ----------------
__global__ __launch_bounds__(256, 2) void mega_gemm_kernel(
    const float* __restrict__ bias, float* __restrict__ out)
{
    extern __shared__ __align__(1024) char dsm[];
    __shared__ float s_bias[TILE_N];

    const int tid = threadIdx.x;
    const int wid = tid >> 5;
    const int lane = tid & 31;
    const int wm = wid >> 2;            // 0..1  -> 64-row half
    const int wn = wid & 3;             // 0..3  -> 32-col slice
    const int bo = blockIdx.x * TILE_N;
    const int bt = blockIdx.y * TILE_M;

    const uint32_t smb = smem_u32(dsm);
    if (tid < TILE_N) s_bias[tid] = bias[bo + tid];

    float acc[4][4][4];
#pragma unroll
    for (int i = 0; i < 4; i++)
#pragma unroll
        for (int j = 0; j < 4; j++)
#pragma unroll
            for (int q = 0; q < 4; q++) acc[i][j][q] = 0.f;

    // ---- async-load one K chunk into stage s ----
    auto load_chunk = [&](int k, int s) {
        const uint32_t sb = smb + s * STAGE_BYTES;
        const __half *Asrc, *Bsrc;
        size_t astr, bstr;
        if (k < NCHUNK_BASE) {
            Asrc = g_xh + (size_t)bt * D_IN + k * KC;
            Bsrc = g_wh + (size_t)bo * D_IN + k * KC;
            astr = D_IN; bstr = D_IN;
        } else {
            int kc = k - NCHUNK_BASE;
            Asrc = g_C + (size_t)bt * 128 + kc * KC;
            Bsrc = g_L + (size_t)bo * 128 + kc * KC;
            astr = 128; bstr = 128;
        }
#pragma unroll
        for (int it = 0; it < 4; it++) {
            int i = tid + it * 256;
            int row = i >> 3, g = i & 7;
            uint32_t off = (uint32_t)(row * 128) + ((uint32_t)(g ^ (row & 7)) << 4);
            cp16(sb + off, Asrc + (size_t)row * astr + g * 8);
            cp16(sb + A_BYTES + off, Bsrc + (size_t)row * bstr + g * 8);
        }
        cp_commit();
    };

    load_chunk(0, 0);

    for (int k = 0; k < NCHUNK; k++) {
        const int s = k & 1;
        if (k + 1 < NCHUNK) { load_chunk(k + 1, s ^ 1); cp_wait1(); }
        else                { cp_wait0(); }
        __syncthreads();

        const uint32_t sA = smb + s * STAGE_BYTES;
        const uint32_t sB = sA + A_BYTES;

#pragma unroll
        for (int ks = 0; ks < 4; ks++) {
            // A fragments: 4 m16 tiles
            uint32_t a[4][4];
#pragma unroll
            for (int mi = 0; mi < 4; mi++) {
                int row = wm * 64 + mi * 16 + (lane & 15);
                int chunk = ks * 2 + (lane >> 4);
                uint32_t addr = sA + (uint32_t)(row * 128) + ((uint32_t)(chunk ^ (row & 7)) << 4);
                ldsm_x4(a[mi], addr);
            }
            // B fragments: 4 n8 tiles via 2 x4 loads
            uint32_t b[4][2];
#pragma unroll
            for (int pr = 0; pr < 2; pr++) {
                int nrow = wn * 32 + pr * 16 + (lane & 7) + ((lane >> 4) << 3);
                int chunk = ks * 2 + ((lane >> 3) & 1);
                uint32_t addr = sB + (uint32_t)(nrow * 128) + ((uint32_t)(chunk ^ (nrow & 7)) << 4);
                uint32_t r4[4];
                ldsm_x4(r4, addr);
                b[pr * 2 + 0][0] = r4[0]; b[pr * 2 + 0][1] = r4[1];
                b[pr * 2 + 1][0] = r4[2]; b[pr * 2 + 1][1] = r4[3];
            }
#pragma unroll
            for (int mi = 0; mi < 4; mi++)
#pragma unroll
                for (int ni = 0; ni < 4; ni++)
                    mma16816(acc[mi][ni], a[mi], b[ni][0], b[ni][1]);
        }
        __syncthreads();
    }

    // ---- epilogue: registers -> gmem with bias ----
    const int gq = lane >> 2;       // 0..7 row-in-tile group
    const int cq = (lane & 3) * 2;  // col pair
#pragma unroll
    for (int mi = 0; mi < 4; mi++) {
        int r0 = bt + wm * 64 + mi * 16 + gq;
#pragma unroll
        for (int ni = 0; ni < 4; ni++) {
            int c0 = bo + wn * 32 + ni * 8 + cq;
            float bx = s_bias[c0 - bo], by = s_bias[c0 - bo + 1];
            float2 v0 = make_float2(acc[mi][ni][0] + bx, acc[mi][ni][1] + by);
            float2 v1 = make_float2(acc[mi][ni][2] + bx, acc[mi][ni][3] + by);
            *(float2*)(out + (size_t)r0 * D_OUT + c0) = v0;
            *(float2*)(out + (size_t)(r0 + 8) * D_OUT + c0) = v1;
        }
    }
}

// ---------------- launch ----------------
extern "C" void kernel_launch(void* const* d_in, const int* in_sizes, int n_in,
                              void* d_out, int out_size)
{
    const float* x      = (const float*)d_in[0];
    const float* gate_w = (const float*)d_in[1];
    const float* base_w = (const float*)d_in[2];
    const float* base_b = (const float*)d_in[3];
    const float* lora_A = (const float*)d_in[4];
    const float* lora_B = (const float*)d_in[5];
    float* out = (float*)d_out;

    cudaFuncSetAttribute(mega_gemm_kernel, cudaFuncAttributeMaxDynamicSharedMemorySize,
                         NSTAGE * STAGE_BYTES);

    __half *xh, *wh;
    cudaGetSymbolAddress((void**)&xh, g_xh);
    cudaGetSymbolAddress((void**)&wh, g_wh);

    const int n4x = (T_TOK * D_IN) / 4;
    tohalf_kernel<<<(n4x + 255) / 256, 256>>>(x, xh, n4x);
    const int n4w = (D_OUT * D_IN) / 4;
    tohalf_kernel<<<(n4w + 255) / 256, 256>>>(base_w, wh, n4w);
    pack_L_kernel<<<(D_OUT * 128 + 255) / 256, 256>>>(lora_B);

    gate_low_kernel<<<T_TOK / 32, 256>>>(x, gate_w, lora_A);
    route_kernel<<<(T_TOK + 255) / 256, 256>>>();

    mega_gemm_kernel<<<dim3(D_OUT / TILE_N, T_TOK / TILE_M), 256, NSTAGE * STAGE_BYTES>>>(base_b, out);
}

// round 4
// speedup vs baseline: 11.2688x; 2.8080x over previous
#include <cuda_runtime.h>
#include <cuda_fp16.h>
#include <math.h>
#include <stdint.h>

// ---------------- problem constants ----------------
#define T_TOK   4096
#define D_IN    4096
#define D_OUT   4096
#define N_EXP   8
#define RANK    16
#define SCALING 2.0f
#define NJ      (N_EXP + N_EXP*RANK)   // 136

// ---------------- mega GEMM tiling ----------------
#define TILE_M  128
#define TILE_N  128
#define KC      64                     // fp16 K elems per chunk (128 B rows)
#define NCHUNK_BASE (D_IN / KC)        // 64
#define NCHUNK  (NCHUNK_BASE + 2)      // + 2 LoRA chunks

#define A_BYTES (TILE_M * 128)         // 16 KB
#define B_BYTES (TILE_N * 128)         // 16 KB
#define STAGE_BYTES (A_BYTES + B_BYTES)
#define NSTAGE  2

// ---------------- gate GEMM (N=136) ----------------
#define GN      136
#define GB_BYTES (GN * 128)            // 17408
#define GSTAGE_BYTES (A_BYTES + GB_BYTES)
#define NSPLIT  4
#define GCHUNKS (NCHUNK_BASE / NSPLIT) // 16 chunks per K slice

// ---------------- device scratch ----------------
__device__ __half g_xh[(size_t)T_TOK * D_IN];
__device__ __half g_wh[(size_t)D_OUT * D_IN];
__device__ __half g_W2[(size_t)NJ * D_IN];          // packed [gate_w; lora_A] fp16
__device__ __half g_L [(size_t)D_OUT * 128];
__device__ __half g_C [(size_t)T_TOK * 128];
__device__ float  g_part[(size_t)NSPLIT * T_TOK * NJ];

// ---------------- helpers ----------------
__device__ __forceinline__ uint32_t smem_u32(const void* p) {
    uint32_t a;
    asm("{ .reg .u64 t; cvta.to.shared.u64 t, %1; cvt.u32.u64 %0, t; }" : "=r"(a) : "l"(p));
    return a;
}
__device__ __forceinline__ void cp16(uint32_t dst, const void* src) {
    asm volatile("cp.async.cg.shared.global [%0], [%1], 16;" :: "r"(dst), "l"(src));
}
__device__ __forceinline__ void cp_commit() { asm volatile("cp.async.commit_group;" ::: "memory"); }
__device__ __forceinline__ void cp_wait1()  { asm volatile("cp.async.wait_group 1;" ::: "memory"); }
__device__ __forceinline__ void cp_wait0()  { asm volatile("cp.async.wait_group 0;" ::: "memory"); }

__device__ __forceinline__ void ldsm_x4(uint32_t (&r)[4], uint32_t addr) {
    asm volatile("ldmatrix.sync.aligned.m8n8.x4.shared.b16 {%0,%1,%2,%3}, [%4];"
                 : "=r"(r[0]), "=r"(r[1]), "=r"(r[2]), "=r"(r[3]) : "r"(addr));
}
__device__ __forceinline__ void ldsm_x2(uint32_t (&r)[2], uint32_t addr) {
    asm volatile("ldmatrix.sync.aligned.m8n8.x2.shared.b16 {%0,%1}, [%2];"
                 : "=r"(r[0]), "=r"(r[1]) : "r"(addr));
}
__device__ __forceinline__ void mma16816(float (&d)[4], const uint32_t (&a)[4], const uint32_t b0, const uint32_t b1) {
    asm volatile(
        "mma.sync.aligned.m16n8k16.row.col.f32.f16.f16.f32 "
        "{%0,%1,%2,%3},{%4,%5,%6,%7},{%8,%9},{%0,%1,%2,%3};"
        : "+f"(d[0]), "+f"(d[1]), "+f"(d[2]), "+f"(d[3])
        : "r"(a[0]), "r"(a[1]), "r"(a[2]), "r"(a[3]), "r"(b0), "r"(b1));
}

// ---------------- convert f32 -> fp16 ----------------
__global__ __launch_bounds__(256) void tohalf_kernel(
    const float* __restrict__ src, __half* __restrict__ dst, int n4)
{
    int i = blockIdx.x * 256 + threadIdx.x;
    if (i >= n4) return;
    float4 v = ((const float4*)src)[i];
    ((__half2*)dst)[i * 2]     = __floats2half2_rn(v.x, v.y);
    ((__half2*)dst)[i * 2 + 1] = __floats2half2_rn(v.z, v.w);
}

// ---------------- pack lora_B [E,O,R] -> L[o, e*16+r] fp16 ----------------
__global__ __launch_bounds__(256) void pack_L_kernel(const float* __restrict__ lora_B)
{
    int idx = blockIdx.x * 256 + threadIdx.x;
    if (idx >= D_OUT * 128) return;
    int o = idx >> 7, j = idx & 127;
    int e = j >> 4, r = j & 15;
    g_L[idx] = __float2half(lora_B[((size_t)e * D_OUT + o) * RANK + r]);
}

// ---------------- pack [gate_w; lora_A] -> W2[136][4096] fp16 ----------------
__global__ __launch_bounds__(256) void pack_W2_kernel(
    const float* __restrict__ gate_w, const float* __restrict__ lora_A)
{
    int idx = blockIdx.x * 256 + threadIdx.x;     // over NJ * D_IN
    if (idx >= NJ * D_IN) return;
    int row = idx / D_IN, d = idx % D_IN;
    float v = (row < N_EXP) ? gate_w[(size_t)row * D_IN + d]
                            : lora_A[(size_t)(row - N_EXP) * D_IN + d];
    g_W2[idx] = __float2half(v);
}

// ---------------- kernel G1: low/gate GEMM  part[s] = x[:,Kslice] @ W2[:,Kslice]^T ----------------
// TILE_M=128, N=136 (17 n8 tiles), 8 warps x m16, split-K over grid.x
__global__ __launch_bounds__(256, 1) void gate_gemm_kernel()
{
    extern __shared__ __align__(1024) char dsm[];
    const int tid = threadIdx.x;
    const int wid = tid >> 5;
    const int lane = tid & 31;
    const int split = blockIdx.x;
    const int bt = blockIdx.y * TILE_M;
    const int k0 = split * GCHUNKS;

    const uint32_t smb = smem_u32(dsm);

    float acc[17][4];
#pragma unroll
    for (int i = 0; i < 17; i++)
#pragma unroll
        for (int q = 0; q < 4; q++) acc[i][q] = 0.f;

    auto load_chunk = [&](int kk, int s) {
        const uint32_t sb = smb + s * GSTAGE_BYTES;
        const __half* Asrc = g_xh + (size_t)bt * D_IN + (k0 + kk) * KC;
        const __half* Bsrc = g_W2 + (size_t)(k0 + kk) * KC;
        // A: 128 rows x 8 groups
#pragma unroll
        for (int it = 0; it < 4; it++) {
            int i = tid + it * 256;
            int row = i >> 3, g = i & 7;
            uint32_t off = (uint32_t)(row * 128) + ((uint32_t)(g ^ (row & 7)) << 4);
            cp16(sb + off, Asrc + (size_t)row * D_IN + g * 8);
        }
        // B: 136 rows x 8 groups = 1088
#pragma unroll
        for (int it = 0; it < 5; it++) {
            int i = tid + it * 256;
            if (i < GN * 8) {
                int row = i >> 3, g = i & 7;
                uint32_t off = (uint32_t)(row * 128) + ((uint32_t)(g ^ (row & 7)) << 4);
                cp16(sb + A_BYTES + off, Bsrc + (size_t)row * D_IN + g * 8);
            }
        }
        cp_commit();
    };

    load_chunk(0, 0);

    for (int kk = 0; kk < GCHUNKS; kk++) {
        const int s = kk & 1;
        if (kk + 1 < GCHUNKS) { load_chunk(kk + 1, s ^ 1); cp_wait1(); }
        else                  { cp_wait0(); }
        __syncthreads();

        const uint32_t sA = smb + s * GSTAGE_BYTES;
        const uint32_t sB = sA + A_BYTES;

#pragma unroll
        for (int ks = 0; ks < 4; ks++) {
            uint32_t a[4];
            {
                int row = wid * 16 + (lane & 15);
                int chunk = ks * 2 + (lane >> 4);
                ldsm_x4(a, sA + (uint32_t)(row * 128) + ((uint32_t)(chunk ^ (row & 7)) << 4));
            }
            uint32_t b[17][2];
#pragma unroll
            for (int pr = 0; pr < 8; pr++) {
                int nrow = pr * 16 + (lane & 7) + ((lane >> 4) << 3);
                int chunk = ks * 2 + ((lane >> 3) & 1);
                uint32_t r4[4];
                ldsm_x4(r4, sB + (uint32_t)(nrow * 128) + ((uint32_t)(chunk ^ (nrow & 7)) << 4));
                b[pr * 2 + 0][0] = r4[0]; b[pr * 2 + 0][1] = r4[1];
                b[pr * 2 + 1][0] = r4[2]; b[pr * 2 + 1][1] = r4[3];
            }
            {
                // last 8 N rows (128..135): x2
                int nrow = 128 + (lane & 7);
                int chunk = ks * 2 + ((lane >> 3) & 1);
                uint32_t r2[2];
                ldsm_x2(r2, sB + (uint32_t)(nrow * 128) + ((uint32_t)(chunk ^ (nrow & 7)) << 4));
                b[16][0] = r2[0]; b[16][1] = r2[1];
            }
#pragma unroll
            for (int ni = 0; ni < 17; ni++)
                mma16816(acc[ni], a, b[ni][0], b[ni][1]);
        }
        __syncthreads();
    }

    // epilogue -> g_part[split][t][136]
    const int gq = lane >> 2;
    const int cq = (lane & 3) * 2;
    const int r0 = bt + wid * 16 + gq;
    float* p0 = g_part + ((size_t)split * T_TOK + r0) * NJ;
    float* p1 = g_part + ((size_t)split * T_TOK + r0 + 8) * NJ;
#pragma unroll
    for (int ni = 0; ni < 17; ni++) {
        int c0 = ni * 8 + cq;
        *(float2*)(p0 + c0) = make_float2(acc[ni][0], acc[ni][1]);
        *(float2*)(p1 + c0) = make_float2(acc[ni][2], acc[ni][3]);
    }
}

// ---------------- kernel G2: reduce partials + top-2 softmax -> C[t,128] fp16 ----------------
__global__ __launch_bounds__(NJ) void route_kernel()
{
    __shared__ float lg[NJ];
    __shared__ float s_w[2];
    __shared__ int   s_i[2];
    const int t = blockIdx.x;
    const int j = threadIdx.x;

    float v = 0.f;
#pragma unroll
    for (int s = 0; s < NSPLIT; s++)
        v += g_part[((size_t)s * T_TOK + t) * NJ + j];
    lg[j] = v;
    __syncthreads();

    if (j == 0) {
        int i0 = 0; float v0 = lg[0];
#pragma unroll
        for (int e = 1; e < N_EXP; e++) { float w = lg[e]; if (w > v0) { v0 = w; i0 = e; } }
        int i1 = -1; float v1 = -INFINITY;
#pragma unroll
        for (int e = 0; e < N_EXP; e++) {
            if (e == i0) continue;
            float w = lg[e];
            if (w > v1) { v1 = w; i1 = e; }
        }
        float e1 = expf(v1 - v0);
        float w0 = 1.f / (1.f + e1);
        s_w[0] = SCALING * w0;
        s_w[1] = SCALING * e1 * w0;
        s_i[0] = i0; s_i[1] = i1;
    }
    __syncthreads();

    if (j < 128) {
        int e = j >> 4;
        float w = (e == s_i[0]) ? s_w[0] : (e == s_i[1]) ? s_w[1] : 0.f;
        g_C[(size_t)t * 128 + j] = __float2half(w * lg[N_EXP + j]);
    }
}

// ---------------- kernel 3: fused fp16 HMMA GEMM: out = x@W^T + b + C@L^T ----------------
__global__ __launch_bounds__(256, 2) void mega_gemm_kernel(
    const float* __restrict__ bias, float* __restrict__ out)
{
    extern __shared__ __align__(1024) char dsm[];
    __shared__ float s_bias[TILE_N];

    const int tid = threadIdx.x;
    const int wid = tid >> 5;
    const int lane = tid & 31;
    const int wm = wid >> 2;
    const int wn = wid & 3;
    const int bo = blockIdx.x * TILE_N;
    const int bt = blockIdx.y * TILE_M;

    const uint32_t smb = smem_u32(dsm);
    if (tid < TILE_N) s_bias[tid] = bias[bo + tid];

    float acc[4][4][4];
#pragma unroll
    for (int i = 0; i < 4; i++)
#pragma unroll
        for (int j = 0; j < 4; j++)
#pragma unroll
            for (int q = 0; q < 4; q++) acc[i][j][q] = 0.f;

    auto load_chunk = [&](int k, int s) {
        const uint32_t sb = smb + s * STAGE_BYTES;
        const __half *Asrc, *Bsrc;
        size_t astr, bstr;
        if (k < NCHUNK_BASE) {
            Asrc = g_xh + (size_t)bt * D_IN + k * KC;
            Bsrc = g_wh + (size_t)bo * D_IN + k * KC;
            astr = D_IN; bstr = D_IN;
        } else {
            int kc = k - NCHUNK_BASE;
            Asrc = g_C + (size_t)bt * 128 + kc * KC;
            Bsrc = g_L + (size_t)bo * 128 + kc * KC;
            astr = 128; bstr = 128;
        }
#pragma unroll
        for (int it = 0; it < 4; it++) {
            int i = tid + it * 256;
            int row = i >> 3, g = i & 7;
            uint32_t off = (uint32_t)(row * 128) + ((uint32_t)(g ^ (row & 7)) << 4);
            cp16(sb + off, Asrc + (size_t)row * astr + g * 8);
            cp16(sb + A_BYTES + off, Bsrc + (size_t)row * bstr + g * 8);
        }
        cp_commit();
    };

    load_chunk(0, 0);

    for (int k = 0; k < NCHUNK; k++) {
        const int s = k & 1;
        if (k + 1 < NCHUNK) { load_chunk(k + 1, s ^ 1); cp_wait1(); }
        else                { cp_wait0(); }
        __syncthreads();

        const uint32_t sA = smb + s * STAGE_BYTES;
        const uint32_t sB = sA + A_BYTES;

#pragma unroll
        for (int ks = 0; ks < 4; ks++) {
            uint32_t a[4][4];
#pragma unroll
            for (int mi = 0; mi < 4; mi++) {
                int row = wm * 64 + mi * 16 + (lane & 15);
                int chunk = ks * 2 + (lane >> 4);
                ldsm_x4(a[mi], sA + (uint32_t)(row * 128) + ((uint32_t)(chunk ^ (row & 7)) << 4));
            }
            uint32_t b[4][2];
#pragma unroll
            for (int pr = 0; pr < 2; pr++) {
                int nrow = wn * 32 + pr * 16 + (lane & 7) + ((lane >> 4) << 3);
                int chunk = ks * 2 + ((lane >> 3) & 1);
                uint32_t r4[4];
                ldsm_x4(r4, sB + (uint32_t)(nrow * 128) + ((uint32_t)(chunk ^ (nrow & 7)) << 4));
                b[pr * 2 + 0][0] = r4[0]; b[pr * 2 + 0][1] = r4[1];
                b[pr * 2 + 1][0] = r4[2]; b[pr * 2 + 1][1] = r4[3];
            }
#pragma unroll
            for (int mi = 0; mi < 4; mi++)
#pragma unroll
                for (int ni = 0; ni < 4; ni++)
                    mma16816(acc[mi][ni], a[mi], b[ni][0], b[ni][1]);
        }
        __syncthreads();
    }

    const int gq = lane >> 2;
    const int cq = (lane & 3) * 2;
#pragma unroll
    for (int mi = 0; mi < 4; mi++) {
        int r0 = bt + wm * 64 + mi * 16 + gq;
#pragma unroll
        for (int ni = 0; ni < 4; ni++) {
            int c0 = bo + wn * 32 + ni * 8 + cq;
            float bx = s_bias[c0 - bo], by = s_bias[c0 - bo + 1];
            *(float2*)(out + (size_t)r0 * D_OUT + c0)       = make_float2(acc[mi][ni][0] + bx, acc[mi][ni][1] + by);
            *(float2*)(out + (size_t)(r0 + 8) * D_OUT + c0) = make_float2(acc[mi][ni][2] + bx, acc[mi][ni][3] + by);
        }
    }
}

// ---------------- launch ----------------
extern "C" void kernel_launch(void* const* d_in, const int* in_sizes, int n_in,
                              void* d_out, int out_size)
{
    const float* x      = (const float*)d_in[0];
    const float* gate_w = (const float*)d_in[1];
    const float* base_w = (const float*)d_in[2];
    const float* base_b = (const float*)d_in[3];
    const float* lora_A = (const float*)d_in[4];
    const float* lora_B = (const float*)d_in[5];
    float* out = (float*)d_out;

    cudaFuncSetAttribute(mega_gemm_kernel, cudaFuncAttributeMaxDynamicSharedMemorySize,
                         NSTAGE * STAGE_BYTES);
    cudaFuncSetAttribute(gate_gemm_kernel, cudaFuncAttributeMaxDynamicSharedMemorySize,
                         NSTAGE * GSTAGE_BYTES);

    __half *xh, *wh;
    cudaGetSymbolAddress((void**)&xh, g_xh);
    cudaGetSymbolAddress((void**)&wh, g_wh);

    const int n4x = (T_TOK * D_IN) / 4;
    tohalf_kernel<<<(n4x + 255) / 256, 256>>>(x, xh, n4x);
    const int n4w = (D_OUT * D_IN) / 4;
    tohalf_kernel<<<(n4w + 255) / 256, 256>>>(base_w, wh, n4w);
    pack_L_kernel<<<(D_OUT * 128 + 255) / 256, 256>>>(lora_B);
    pack_W2_kernel<<<(NJ * D_IN + 255) / 256, 256>>>(gate_w, lora_A);

    gate_gemm_kernel<<<dim3(NSPLIT, T_TOK / TILE_M), 256, NSTAGE * GSTAGE_BYTES>>>();
    route_kernel<<<T_TOK, NJ>>>();

    mega_gemm_kernel<<<dim3(D_OUT / TILE_N, T_TOK / TILE_M), 256, NSTAGE * STAGE_BYTES>>>(base_b, out);
}